// round 1
// baseline (speedup 1.0000x reference)
#include <cuda_runtime.h>
#include <cuda_bf16.h>
#include <cstdint>

// Problem constants (shape-fixed problem)
#define BB 2
#define LL 1024
#define D_EMB 64
#define D_MODEL 128
#define ROWS (BB * LL)           // 2048

// Scratch: separable precompute results. float4 arrays guarantee 16B alignment.
__device__ float4 g_P[ROWS * (D_MODEL / 4)];   // P[b,l,d] = bias[d] + sum_c e*W[d,c]      (1 MB)
__device__ float4 g_Q[ROWS * (D_MODEL / 4)];   // Q[b,l,d] = sum_c e*W[d,64+c]             (1 MB)
__device__ float4 g_W128[D_MODEL / 4];         // packed W[:,128] column

// ---------------------------------------------------------------------------
// Kernel 1: precompute P, Q, and pack W[:,128].
// grid = 2048 blocks (one per (b,l) row), 128 threads (one per d).
// ---------------------------------------------------------------------------
__global__ __launch_bounds__(128) void precompute_kernel(
    const int* __restrict__ seq,
    const float* __restrict__ emb,     // [21, 64]
    const float* __restrict__ W,       // [128, 129] row-major
    const float* __restrict__ bias)    // [128]
{
    const int row = blockIdx.x;        // b*L + l
    const int d = threadIdx.x;

    __shared__ float e[D_EMB];
    if (d < D_EMB) {
        int s = seq[row];
        e[d] = emb[s * D_EMB + d];
    }
    __syncthreads();

    const float* wrow = W + d * 129;
    float accP = bias[d];
    float accQ = 0.0f;
#pragma unroll
    for (int c = 0; c < D_EMB; c++) {
        accP = fmaf(e[c], wrow[c], accP);
        accQ = fmaf(e[c], wrow[D_EMB + c], accQ);
    }
    ((float*)g_P)[row * D_MODEL + d] = accP;
    ((float*)g_Q)[row * D_MODEL + d] = accQ;
    if (row == 0) {
        ((float*)g_W128)[d] = wrow[2 * D_EMB];   // W[d, 128]
    }
}

// ---------------------------------------------------------------------------
// Kernel 2: out[b,i,j,d] = P[b,i,d] + Q[b,j,d] + log(|idx_i-idx_j|+1)*W128[d]
// 256 threads = 8 warps. Warp owns (b,i) and NJ=16 consecutive j's.
// Lane t owns float4 d = 4t..4t+3. Pure streaming-store kernel.
// grid = B * L * 8 = 16384 blocks.
// ---------------------------------------------------------------------------
#define NWARP 8
#define NJ 16                          // j's per warp; NWARP*NJ = 128 j's per block
#define JCHUNKS (LL / (NWARP * NJ))    // 8

__global__ __launch_bounds__(256) void pair_kernel(
    const int* __restrict__ idx,
    float4* __restrict__ out)
{
    const int blk = blockIdx.x;
    const int chunk = blk & (JCHUNKS - 1);          // 0..7
    const int i = (blk >> 3) & (LL - 1);            // 0..1023
    const int b = blk >> 13;                        // 0..1

    const int w = threadIdx.x >> 5;                 // warp 0..7
    const int t = threadIdx.x & 31;                 // lane -> d4 index

    const int rowi = b * LL + i;

    const float4 p4 = g_P[rowi * 32 + t];
    const float4 w4 = g_W128[t];
    const int idx_i = __ldg(idx + rowi);

    const int j0 = chunk * (NWARP * NJ) + w * NJ;
    const float4* __restrict__ Qb = g_Q + (size_t)b * LL * 32;
    const int* __restrict__ idxb = idx + b * LL;
    float4* __restrict__ outb = out + (size_t)rowi * LL * 32;

#pragma unroll 4
    for (int k = 0; k < NJ; k++) {
        const int j = j0 + k;
        const int idx_j = __ldg(idxb + j);
        const float s = __logf(fabsf((float)(idx_i - idx_j)) + 1.0f);
        const float4 q = Qb[(size_t)j * 32 + t];
        float4 o;
        o.x = fmaf(s, w4.x, p4.x + q.x);
        o.y = fmaf(s, w4.y, p4.y + q.y);
        o.z = fmaf(s, w4.z, p4.z + q.z);
        o.w = fmaf(s, w4.w, p4.w + q.w);
        outb[(size_t)j * 32 + t] = o;
    }
}

// ---------------------------------------------------------------------------
// Launch: inputs per metadata order: seq(int32), idx(int32), emb_table(f32),
// W(f32 [128,129]), b(f32 [128]). Output: f32 [2,1024,1024,128].
// ---------------------------------------------------------------------------
extern "C" void kernel_launch(void* const* d_in, const int* in_sizes, int n_in,
                              void* d_out, int out_size)
{
    const int*   seq  = (const int*)d_in[0];
    const int*   idx  = (const int*)d_in[1];
    const float* emb  = (const float*)d_in[2];
    const float* W    = (const float*)d_in[3];
    const float* bias = (const float*)d_in[4];
    float4* out = (float4*)d_out;

    precompute_kernel<<<ROWS, 128>>>(seq, emb, W, bias);
    pair_kernel<<<BB * LL * JCHUNKS, 256>>>(idx, out);
}

// round 2
// speedup vs baseline: 1.2149x; 1.2149x over previous
#include <cuda_runtime.h>
#include <cuda_bf16.h>
#include <cstdint>

// Problem constants (shape-fixed problem)
#define BB 2
#define LL 1024
#define D_SEQ 21
#define D_EMB 64
#define D_MODEL 128
#define ROWS (BB * LL)           // 2048

// Per-symbol separable tables (seq values are in [0, 21)).
__device__ float4 g_TP[D_SEQ * (D_MODEL / 4)];   // T_P[s,d] = bias[d] + sum_c emb[s,c]*W[d,c]
__device__ float4 g_TQ[D_SEQ * (D_MODEL / 4)];   // T_Q[s,d] = sum_c emb[s,c]*W[d,64+c]
__device__ float4 g_W128[D_MODEL / 4];           // packed W[:,128] column

// ---------------------------------------------------------------------------
// Kernel 1: per-symbol table precompute. 21 blocks x 128 threads.
// ---------------------------------------------------------------------------
__global__ __launch_bounds__(128) void table_kernel(
    const float* __restrict__ emb,     // [21, 64]
    const float* __restrict__ W,       // [128, 129] row-major
    const float* __restrict__ bias)    // [128]
{
    const int s = blockIdx.x;          // symbol 0..20
    const int d = threadIdx.x;         // 0..127

    __shared__ float e[D_EMB];
    if (d < D_EMB) e[d] = emb[s * D_EMB + d];
    __syncthreads();

    const float* wrow = W + d * 129;
    float accP = bias[d];
    float accQ = 0.0f;
#pragma unroll
    for (int c = 0; c < D_EMB; c++) {
        accP = fmaf(e[c], wrow[c], accP);
        accQ = fmaf(e[c], wrow[D_EMB + c], accQ);
    }
    ((float*)g_TP)[s * D_MODEL + d] = accP;
    ((float*)g_TQ)[s * D_MODEL + d] = accQ;
    if (s == 0) ((float*)g_W128)[d] = wrow[2 * D_EMB];   // W[d, 128]
}

// ---------------------------------------------------------------------------
// Kernel 2: out[b,i,j,d] = T_P[seq_i,d] + T_Q[seq_j,d] + log(|idx_i-idx_j|+1)*W128[d]
// One block per (b,i) row. 256 threads = 8 warps; warp w owns j in
// [w*128, w*128+128). Lane t owns float4 d = 4t..4t+3.
// T_Q staged in shared memory -> zero L1/L2 read traffic in the hot loop.
// ---------------------------------------------------------------------------
#define NWARP 8
#define JPW (LL / NWARP)      // 128 j's per warp

__global__ __launch_bounds__(256) void pair_kernel(
    const int* __restrict__ seq,
    const int* __restrict__ idx,
    float4* __restrict__ out)
{
    const int rowi = blockIdx.x;            // b*L + i
    const int b = rowi >> 10;
    const int w = threadIdx.x >> 5;
    const int t = threadIdx.x & 31;

    __shared__ float4 sQ[D_SEQ * 32];       // 10.75 KB
    for (int k = threadIdx.x; k < D_SEQ * 32; k += 256) sQ[k] = g_TQ[k];
    __syncthreads();

    const float4 p4 = g_TP[__ldg(seq + rowi) * 32 + t];
    const float4 w4 = g_W128[t];
    const int idx_i = __ldg(idx + rowi);

    const int* __restrict__ idxb = idx + b * LL;
    const int* __restrict__ seqb = seq + b * LL;
    float4* __restrict__ outb = out + (size_t)rowi * LL * 32;

    const int j0 = w * JPW;
#pragma unroll 4
    for (int k = 0; k < JPW; k++) {
        const int j = j0 + k;
        const int sj = __ldg(seqb + j);
        const int idx_j = __ldg(idxb + j);
        const float s = __logf(fabsf((float)(idx_i - idx_j)) + 1.0f);
        const float4 q = sQ[sj * 32 + t];
        float4 o;
        o.x = fmaf(s, w4.x, p4.x + q.x);
        o.y = fmaf(s, w4.y, p4.y + q.y);
        o.z = fmaf(s, w4.z, p4.z + q.z);
        o.w = fmaf(s, w4.w, p4.w + q.w);
        __stcs(&outb[(size_t)j * 32 + t], o);
    }
}

// ---------------------------------------------------------------------------
// Launch: inputs per metadata order: seq(int32), idx(int32), emb_table(f32),
// W(f32 [128,129]), b(f32 [128]). Output: f32 [2,1024,1024,128].
// ---------------------------------------------------------------------------
extern "C" void kernel_launch(void* const* d_in, const int* in_sizes, int n_in,
                              void* d_out, int out_size)
{
    const int*   seq  = (const int*)d_in[0];
    const int*   idx  = (const int*)d_in[1];
    const float* emb  = (const float*)d_in[2];
    const float* W    = (const float*)d_in[3];
    const float* bias = (const float*)d_in[4];
    float4* out = (float4*)d_out;

    table_kernel<<<D_SEQ, 128>>>(emb, W, bias);
    pair_kernel<<<ROWS, 256>>>(seq, idx, out);
}